// round 6
// baseline (speedup 1.0000x reference)
#include <cuda_runtime.h>
#include <cstdint>

#define NN 20000     // nodes
#define CI 128       // in channels
#define TT 8         // time steps
#define CO 64        // out channels
#define EE 160000    // edges

// ---------------- scratch (static device globals; no allocation) ----------------
__device__ double   g_sum[CI];
__device__ double   g_sumsq[CI];
__device__ float    g_mean[CI];
__device__ float    g_rs[CI];                 // rsqrt(var + eps)
__device__ unsigned g_bits[NN * 32];          // spike bits: [n][t*4+k], bit l = spike(c=l+32k, t)
__device__ int      g_deg[NN];
__device__ float    g_dinv[NN];
__device__ int      g_rowptr[NN + 1];
__device__ int      g_cursor[NN];
__device__ int      g_col[EE];
__device__ float    g_wgt[EE];
__device__ float    g_y1[(size_t)NN * CO * TT];   // s @ W1^T  [n][d][t]
__device__ float    g_lut[16 * 256 * 128];        // lut[g][m][dcomb]; dcomb<64 -> W0, else W1
__device__ int      g_is64;

// ---------------- init ----------------
__global__ void k_zero() {
    int i = blockIdx.x * blockDim.x + threadIdx.x;
    if (i < CI) { g_sum[i] = 0.0; g_sumsq[i] = 0.0; }
    if (i < NN) g_deg[i] = 0;
}

// Detect int64 vs int32 edge_index: int64 little-endian => every odd 32-bit word
// of the first values is a zero high-half.
__global__ void k_detect(const unsigned* __restrict__ ei) {
    __shared__ int s_nz;
    if (threadIdx.x == 0) s_nz = 0;
    __syncthreads();
    for (int i = threadIdx.x; i < 256; i += blockDim.x)
        if (ei[2 * i + 1] != 0u) atomicOr(&s_nz, 1);
    __syncthreads();
    if (threadIdx.x == 0) g_is64 = (s_nz == 0) ? 1 : 0;
}

// ---------------- BN stats (fp64 accumulate; channel fixed per thread) ----------------
__global__ void k_stats(const float* __restrict__ x) {
    int tid = blockIdx.x * blockDim.x + threadIdx.x;
    int stride = gridDim.x * blockDim.x;   // launch so stride % 128 == 0
    double s = 0.0, q = 0.0;
    for (int r = tid; r < NN * CI; r += stride) {
        const float4* p = (const float4*)(x + (size_t)r * TT);
        float4 a = p[0], b = p[1];
        s += (double)a.x + (double)a.y + (double)a.z + (double)a.w
           + (double)b.x + (double)b.y + (double)b.z + (double)b.w;
        q += (double)a.x * a.x + (double)a.y * a.y + (double)a.z * a.z + (double)a.w * a.w
           + (double)b.x * b.x + (double)b.y * b.y + (double)b.z * b.z + (double)b.w * b.w;
    }
    int c = tid & 127;   // constant per thread because stride % 128 == 0
    atomicAdd(&g_sum[c], s);
    atomicAdd(&g_sumsq[c], q);
}

__global__ void k_final() {
    int c = threadIdx.x;
    if (c < CI) {
        double cnt = (double)NN * (double)TT;
        double m = g_sum[c] / cnt;
        double var = g_sumsq[c] / cnt - m * m;
        g_mean[c] = (float)m;
        g_rs[c] = (float)(1.0 / sqrt(var + 1e-5));
    }
}

// ---------------- LUT build: lut[g][m][d] = sum_{i: bit i of m} W[d][8g+i] ----------------
__global__ void k_lut(const float* __restrict__ W0, const float* __restrict__ W1) {
    int d = threadIdx.x;                  // 0..127 combined output
    int gm = blockIdx.x;                  // g*256 + m
    int g = gm >> 8;
    int m = gm & 255;
    const float* W = (d < CO) ? (W0 + (size_t)d * CI) : (W1 + (size_t)(d - CO) * CI);
    int cb = g * 8;
    float s = 0.f;
#pragma unroll
    for (int i = 0; i < 8; i++)
        if (m & (1 << i)) s += __ldg(&W[cb + i]);
    g_lut[(size_t)gm * 128 + d] = s;
}

// ---------------- normalize + LIF + bit-pack (warp per node) ----------------
__global__ void k_lif(const float* __restrict__ x,
                      const float* __restrict__ gamma,
                      const float* __restrict__ beta) {
    __shared__ float sm[CI], sr[CI], sg[CI], sb[CI];
    int tid = threadIdx.x;
    if (tid < CI) { sm[tid] = g_mean[tid]; sr[tid] = g_rs[tid]; sg[tid] = gamma[tid]; sb[tid] = beta[tid]; }
    __syncthreads();
    int lane = tid & 31;
    int n = blockIdx.x * 8 + (tid >> 5);
    unsigned sp8[4];
#pragma unroll
    for (int k = 0; k < 4; k++) {
        int c = lane + 32 * k;
        const float4* p = (const float4*)(x + (size_t)n * (CI * TT) + (size_t)c * TT);
        float4 a = p[0], b = p[1];
        float m = sm[c], rs = sr[c], ga = sg[c], be = sb[c];
        float h[8];
        // exact reference op order: (gamma*(x-mean))*rsqrt + beta   (no fma contraction)
        h[0] = __fadd_rn(__fmul_rn(__fmul_rn(ga, __fsub_rn(a.x, m)), rs), be);
        h[1] = __fadd_rn(__fmul_rn(__fmul_rn(ga, __fsub_rn(a.y, m)), rs), be);
        h[2] = __fadd_rn(__fmul_rn(__fmul_rn(ga, __fsub_rn(a.z, m)), rs), be);
        h[3] = __fadd_rn(__fmul_rn(__fmul_rn(ga, __fsub_rn(a.w, m)), rs), be);
        h[4] = __fadd_rn(__fmul_rn(__fmul_rn(ga, __fsub_rn(b.x, m)), rs), be);
        h[5] = __fadd_rn(__fmul_rn(__fmul_rn(ga, __fsub_rn(b.y, m)), rs), be);
        h[6] = __fadd_rn(__fmul_rn(__fmul_rn(ga, __fsub_rn(b.z, m)), rs), be);
        h[7] = __fadd_rn(__fmul_rn(__fmul_rn(ga, __fsub_rn(b.w, m)), rs), be);
        float mem = 0.f, spf = 0.f;
        unsigned msk = 0u;
#pragma unroll
        for (int t = 0; t < 8; t++) {
            mem = __fadd_rn(__fmul_rn(__fmul_rn(mem, 0.2f), __fsub_rn(1.f, spf)), h[t]);
            bool s = (mem > 0.5f);
            spf = s ? 1.f : 0.f;
            msk |= (s ? 1u : 0u) << t;
        }
        sp8[k] = msk;
    }
    unsigned myw = 0u;
#pragma unroll
    for (int idx = 0; idx < 32; idx++) {
        unsigned pred = (sp8[idx & 3] >> (idx >> 2)) & 1u;
        unsigned bal = __ballot_sync(0xffffffffu, pred);
        if (lane == idx) myw = bal;
    }
    g_bits[n * 32 + lane] = myw;
}

// ---------------- degree, scan, CSR build ----------------
__global__ void k_deg(const int* __restrict__ ei) {
    int e = blockIdx.x * blockDim.x + threadIdx.x;
    if (e >= EE) return;
    int is64 = g_is64;
    int d = is64 ? ei[2 * (EE + e)] : ei[EE + e];
    atomicAdd(&g_deg[d], 1);
}

__global__ void k_scan() {
    __shared__ int wsum[32];
    __shared__ int s_off;
    int tid = threadIdx.x, lane = tid & 31, w = tid >> 5;
    if (tid == 0) s_off = 0;
    __syncthreads();
    for (int base = 0; base < NN; base += 1024) {
        int i = base + tid;
        int v = (i < NN) ? g_deg[i] : 0;
        int inc = v;
#pragma unroll
        for (int d = 1; d < 32; d <<= 1) {
            int t = __shfl_up_sync(0xffffffffu, inc, d);
            if (lane >= d) inc += t;
        }
        if (lane == 31) wsum[w] = inc;
        __syncthreads();
        if (w == 0) {
            int xv = wsum[lane];
#pragma unroll
            for (int d = 1; d < 32; d <<= 1) {
                int t = __shfl_up_sync(0xffffffffu, xv, d);
                if (lane >= d) xv += t;
            }
            wsum[lane] = xv;
        }
        __syncthreads();
        int off = s_off + (w ? wsum[w - 1] : 0);
        int excl = off + inc - v;
        if (i < NN) {
            g_rowptr[i] = excl;
            g_cursor[i] = excl;
            g_dinv[i] = (v > 0) ? rsqrtf((float)v) : 0.f;
        }
        __syncthreads();
        if (tid == 0) s_off += wsum[31];
        __syncthreads();
    }
    if (threadIdx.x == 0) g_rowptr[NN] = s_off;
}

__global__ void k_csr(const int* __restrict__ ei) {
    int e = blockIdx.x * blockDim.x + threadIdx.x;
    if (e >= EE) return;
    int is64 = g_is64;
    int s = is64 ? ei[2 * e] : ei[e];
    int d = is64 ? ei[2 * (EE + e)] : ei[EE + e];
    int pos = atomicAdd(&g_cursor[d], 1);
    g_col[pos] = s;
    g_wgt[pos] = __fmul_rn(g_dinv[s], g_dinv[d]);
}

// ---------------- GEMM via 8-bit LUT (warp per node) ----------------
// out[n][d][t]      = sum_c s(n,c,t) W0[d][c] + b[d]      (d < 64 half)
// g_y1[n][d][t]     = sum_c s(n,c,t) W1[d][c]             (d >= 64 half)
__global__ void k_gemm(float* __restrict__ out, const float* __restrict__ bias) {
    __shared__ float sbias[CO];
    int tid = threadIdx.x;
    if (tid < CO) sbias[tid] = bias[tid];
    __syncthreads();
    int lane = tid & 31;
    int n = blockIdx.x * 8 + (tid >> 5);
    unsigned myw = g_bits[n * 32 + lane];
    float acc[8][4];
#pragma unroll
    for (int t = 0; t < 8; t++) {
        float ax = 0.f, ay = 0.f, az = 0.f, aw = 0.f;
#pragma unroll
        for (int k = 0; k < 4; k++) {
            unsigned wv = __shfl_sync(0xffffffffu, myw, t * 4 + k);
#pragma unroll
            for (int j = 0; j < 4; j++) {
                unsigned m = (wv >> (8 * j)) & 255u;
                int g = k * 4 + j;
                const float4 v = *(const float4*)(g_lut + ((((unsigned)g << 8) | m) << 7) + (lane << 2));
                ax += v.x; ay += v.y; az += v.z; aw += v.w;
            }
        }
        acc[t][0] = ax; acc[t][1] = ay; acc[t][2] = az; acc[t][3] = aw;
    }
    float* dst;
    float b0, b1, b2, b3;
    if (lane < 16) {
        dst = out + (size_t)n * (CO * TT) + lane * 32;   // d0 = 4*lane, offset d0*8
        b0 = sbias[4 * lane]; b1 = sbias[4 * lane + 1]; b2 = sbias[4 * lane + 2]; b3 = sbias[4 * lane + 3];
    } else {
        dst = g_y1 + (size_t)n * (CO * TT) + (lane - 16) * 32;
        b0 = b1 = b2 = b3 = 0.f;
    }
    float bj[4] = {b0, b1, b2, b3};
#pragma unroll
    for (int j = 0; j < 4; j++) {
        float4 lo = make_float4(acc[0][j] + bj[j], acc[1][j] + bj[j], acc[2][j] + bj[j], acc[3][j] + bj[j]);
        float4 hi = make_float4(acc[4][j] + bj[j], acc[5][j] + bj[j], acc[6][j] + bj[j], acc[7][j] + bj[j]);
        ((float4*)dst)[j * 2] = lo;
        ((float4*)dst)[j * 2 + 1] = hi;
    }
}

// ---------------- atomic-free gather: out[n] += sum_e w_e * y1[src_e] ----------------
__global__ void k_gather(float* __restrict__ out) {
    int n = blockIdx.x;
    int tid = threadIdx.x;   // 128 threads x float4 = 512 floats per node
    int beg = g_rowptr[n], end = g_rowptr[n + 1];
    float4 acc = make_float4(0.f, 0.f, 0.f, 0.f);
    for (int e = beg; e < end; e++) {
        int s = g_col[e];
        float wv = g_wgt[e];
        float4 v = __ldg((const float4*)(g_y1 + (size_t)s * (CO * TT)) + tid);
        acc.x = __fmaf_rn(wv, v.x, acc.x);
        acc.y = __fmaf_rn(wv, v.y, acc.y);
        acc.z = __fmaf_rn(wv, v.z, acc.z);
        acc.w = __fmaf_rn(wv, v.w, acc.w);
    }
    float4* o = (float4*)(out + (size_t)n * (CO * TT)) + tid;
    float4 cur = *o;
    cur.x += acc.x; cur.y += acc.y; cur.z += acc.z; cur.w += acc.w;
    *o = cur;
}

// ---------------- launch ----------------
extern "C" void kernel_launch(void* const* d_in, const int* in_sizes, int n_in,
                              void* d_out, int out_size) {
    const float* x     = (const float*)d_in[0];
    const int*   ei    = (const int*)d_in[1];
    const float* gamma = (const float*)d_in[2];
    const float* beta  = (const float*)d_in[3];
    const float* W0    = (const float*)d_in[4];
    const float* W1    = (const float*)d_in[5];
    const float* bias  = (const float*)d_in[6];
    float* out = (float*)d_out;

    k_zero  <<<(NN + 255) / 256, 256>>>();
    k_detect<<<1, 256>>>((const unsigned*)ei);
    k_stats <<<1024, 256>>>(x);                 // stride 262144 (multiple of 128)
    k_final <<<1, 128>>>();
    k_lut   <<<16 * 256, 128>>>(W0, W1);
    k_lif   <<<NN / 8, 256>>>(x, gamma, beta);
    k_deg   <<<(EE + 255) / 256, 256>>>(ei);
    k_scan  <<<1, 1024>>>();
    k_csr   <<<(EE + 255) / 256, 256>>>(ei);
    k_gemm  <<<NN / 8, 256>>>(out, bias);
    k_gather<<<NN, 128>>>(out);
}

// round 7
// speedup vs baseline: 1.0019x; 1.0019x over previous
#include <cuda_runtime.h>
#include <cstdint>

#define NN 20000     // nodes
#define CI 128       // in channels
#define TT 8         // time steps
#define CO 64        // out channels
#define EE 160000    // edges

// ---------------- scratch (static device globals; no allocation) ----------------
__device__ double   g_sum[CI];
__device__ double   g_sumsq[CI];
__device__ float    g_mean[CI];
__device__ float    g_rs[CI];                 // rsqrt(var + eps)
__device__ unsigned g_bits[NN * 32];          // spike bits: [n][t*4+k], bit l = spike(c=l+32k, t)
__device__ int      g_deg[NN];
__device__ float    g_dinv[NN];
__device__ int      g_rowptr[NN + 1];
__device__ int      g_cursor[NN];
__device__ int      g_col[EE];
__device__ float    g_wgt[EE];
__device__ float    g_y1[(size_t)NN * CO * TT];   // s @ W1^T  [n][d][t]
__device__ float    g_lut[16 * 256 * 128];        // lut[g][m][dcomb]; dcomb<64 -> W0, else W1
__device__ int      g_is64;

// ---------------- init ----------------
__global__ void k_zero() {
    int i = blockIdx.x * blockDim.x + threadIdx.x;
    if (i < CI) { g_sum[i] = 0.0; g_sumsq[i] = 0.0; }
    if (i < NN) g_deg[i] = 0;
}

// Detect int64 vs int32 edge_index: int64 little-endian => every odd 32-bit word
// of the first values is a zero high-half.
__global__ void k_detect(const unsigned* __restrict__ ei) {
    __shared__ int s_nz;
    if (threadIdx.x == 0) s_nz = 0;
    __syncthreads();
    for (int i = threadIdx.x; i < 256; i += blockDim.x)
        if (ei[2 * i + 1] != 0u) atomicOr(&s_nz, 1);
    __syncthreads();
    if (threadIdx.x == 0) g_is64 = (s_nz == 0) ? 1 : 0;
}

// ---------------- BN stats (fp64 accumulate; channel fixed per thread) ----------------
__global__ void k_stats(const float* __restrict__ x) {
    int tid = blockIdx.x * blockDim.x + threadIdx.x;
    int stride = gridDim.x * blockDim.x;   // launch so stride % 128 == 0
    double s = 0.0, q = 0.0;
    for (int r = tid; r < NN * CI; r += stride) {
        const float4* p = (const float4*)(x + (size_t)r * TT);
        float4 a = p[0], b = p[1];
        s += (double)a.x + (double)a.y + (double)a.z + (double)a.w
           + (double)b.x + (double)b.y + (double)b.z + (double)b.w;
        q += (double)a.x * a.x + (double)a.y * a.y + (double)a.z * a.z + (double)a.w * a.w
           + (double)b.x * b.x + (double)b.y * b.y + (double)b.z * b.z + (double)b.w * b.w;
    }
    int c = tid & 127;   // constant per thread because stride % 128 == 0
    atomicAdd(&g_sum[c], s);
    atomicAdd(&g_sumsq[c], q);
}

__global__ void k_final() {
    int c = threadIdx.x;
    if (c < CI) {
        double cnt = (double)NN * (double)TT;
        double m = g_sum[c] / cnt;
        double var = g_sumsq[c] / cnt - m * m;
        g_mean[c] = (float)m;
        g_rs[c] = (float)(1.0 / sqrt(var + 1e-5));
    }
}

// ---------------- LUT build: lut[g][m][d] = sum_{i: bit i of m} W[d][8g+i] ----------------
__global__ void k_lut(const float* __restrict__ W0, const float* __restrict__ W1) {
    int d = threadIdx.x;                  // 0..127 combined output
    int gm = blockIdx.x;                  // g*256 + m
    int g = gm >> 8;
    int m = gm & 255;
    const float* W = (d < CO) ? (W0 + (size_t)d * CI) : (W1 + (size_t)(d - CO) * CI);
    int cb = g * 8;
    float s = 0.f;
#pragma unroll
    for (int i = 0; i < 8; i++)
        if (m & (1 << i)) s += __ldg(&W[cb + i]);
    g_lut[(size_t)gm * 128 + d] = s;
}

// ---------------- normalize + LIF + bit-pack (warp per node) ----------------
__global__ void k_lif(const float* __restrict__ x,
                      const float* __restrict__ gamma,
                      const float* __restrict__ beta) {
    __shared__ float sm[CI], sr[CI], sg[CI], sb[CI];
    int tid = threadIdx.x;
    if (tid < CI) { sm[tid] = g_mean[tid]; sr[tid] = g_rs[tid]; sg[tid] = gamma[tid]; sb[tid] = beta[tid]; }
    __syncthreads();
    int lane = tid & 31;
    int n = blockIdx.x * 8 + (tid >> 5);
    unsigned sp8[4];
#pragma unroll
    for (int k = 0; k < 4; k++) {
        int c = lane + 32 * k;
        const float4* p = (const float4*)(x + (size_t)n * (CI * TT) + (size_t)c * TT);
        float4 a = p[0], b = p[1];
        float m = sm[c], rs = sr[c], ga = sg[c], be = sb[c];
        float h[8];
        // exact reference op order: (gamma*(x-mean))*rsqrt + beta   (no fma contraction)
        h[0] = __fadd_rn(__fmul_rn(__fmul_rn(ga, __fsub_rn(a.x, m)), rs), be);
        h[1] = __fadd_rn(__fmul_rn(__fmul_rn(ga, __fsub_rn(a.y, m)), rs), be);
        h[2] = __fadd_rn(__fmul_rn(__fmul_rn(ga, __fsub_rn(a.z, m)), rs), be);
        h[3] = __fadd_rn(__fmul_rn(__fmul_rn(ga, __fsub_rn(a.w, m)), rs), be);
        h[4] = __fadd_rn(__fmul_rn(__fmul_rn(ga, __fsub_rn(b.x, m)), rs), be);
        h[5] = __fadd_rn(__fmul_rn(__fmul_rn(ga, __fsub_rn(b.y, m)), rs), be);
        h[6] = __fadd_rn(__fmul_rn(__fmul_rn(ga, __fsub_rn(b.z, m)), rs), be);
        h[7] = __fadd_rn(__fmul_rn(__fmul_rn(ga, __fsub_rn(b.w, m)), rs), be);
        float mem = 0.f, spf = 0.f;
        unsigned msk = 0u;
#pragma unroll
        for (int t = 0; t < 8; t++) {
            mem = __fadd_rn(__fmul_rn(__fmul_rn(mem, 0.2f), __fsub_rn(1.f, spf)), h[t]);
            bool s = (mem > 0.5f);
            spf = s ? 1.f : 0.f;
            msk |= (s ? 1u : 0u) << t;
        }
        sp8[k] = msk;
    }
    unsigned myw = 0u;
#pragma unroll
    for (int idx = 0; idx < 32; idx++) {
        unsigned pred = (sp8[idx & 3] >> (idx >> 2)) & 1u;
        unsigned bal = __ballot_sync(0xffffffffu, pred);
        if (lane == idx) myw = bal;
    }
    g_bits[n * 32 + lane] = myw;
}

// ---------------- degree, scan, CSR build ----------------
__global__ void k_deg(const int* __restrict__ ei) {
    int e = blockIdx.x * blockDim.x + threadIdx.x;
    if (e >= EE) return;
    int is64 = g_is64;
    int d = is64 ? ei[2 * (EE + e)] : ei[EE + e];
    atomicAdd(&g_deg[d], 1);
}

__global__ void k_scan() {
    __shared__ int wsum[32];
    __shared__ int s_off;
    int tid = threadIdx.x, lane = tid & 31, w = tid >> 5;
    if (tid == 0) s_off = 0;
    __syncthreads();
    for (int base = 0; base < NN; base += 1024) {
        int i = base + tid;
        int v = (i < NN) ? g_deg[i] : 0;
        int inc = v;
#pragma unroll
        for (int d = 1; d < 32; d <<= 1) {
            int t = __shfl_up_sync(0xffffffffu, inc, d);
            if (lane >= d) inc += t;
        }
        if (lane == 31) wsum[w] = inc;
        __syncthreads();
        if (w == 0) {
            int xv = wsum[lane];
#pragma unroll
            for (int d = 1; d < 32; d <<= 1) {
                int t = __shfl_up_sync(0xffffffffu, xv, d);
                if (lane >= d) xv += t;
            }
            wsum[lane] = xv;
        }
        __syncthreads();
        int off = s_off + (w ? wsum[w - 1] : 0);
        int excl = off + inc - v;
        if (i < NN) {
            g_rowptr[i] = excl;
            g_cursor[i] = excl;
            g_dinv[i] = (v > 0) ? rsqrtf((float)v) : 0.f;
        }
        __syncthreads();
        if (tid == 0) s_off += wsum[31];
        __syncthreads();
    }
    if (threadIdx.x == 0) g_rowptr[NN] = s_off;
}

__global__ void k_csr(const int* __restrict__ ei) {
    int e = blockIdx.x * blockDim.x + threadIdx.x;
    if (e >= EE) return;
    int is64 = g_is64;
    int s = is64 ? ei[2 * e] : ei[e];
    int d = is64 ? ei[2 * (EE + e)] : ei[EE + e];
    int pos = atomicAdd(&g_cursor[d], 1);
    g_col[pos] = s;
    g_wgt[pos] = __fmul_rn(g_dinv[s], g_dinv[d]);
}

// ---------------- GEMM via 8-bit LUT (warp per node) ----------------
// out[n][d][t]      = sum_c s(n,c,t) W0[d][c] + b[d]      (d < 64 half)
// g_y1[n][d][t]     = sum_c s(n,c,t) W1[d][c]             (d >= 64 half)
__global__ void k_gemm(float* __restrict__ out, const float* __restrict__ bias) {
    __shared__ float sbias[CO];
    int tid = threadIdx.x;
    if (tid < CO) sbias[tid] = bias[tid];
    __syncthreads();
    int lane = tid & 31;
    int n = blockIdx.x * 8 + (tid >> 5);
    unsigned myw = g_bits[n * 32 + lane];
    float acc[8][4];
#pragma unroll
    for (int t = 0; t < 8; t++) {
        float ax = 0.f, ay = 0.f, az = 0.f, aw = 0.f;
#pragma unroll
        for (int k = 0; k < 4; k++) {
            unsigned wv = __shfl_sync(0xffffffffu, myw, t * 4 + k);
#pragma unroll
            for (int j = 0; j < 4; j++) {
                unsigned m = (wv >> (8 * j)) & 255u;
                int g = k * 4 + j;
                const float4 v = *(const float4*)(g_lut + ((((unsigned)g << 8) | m) << 7) + (lane << 2));
                ax += v.x; ay += v.y; az += v.z; aw += v.w;
            }
        }
        acc[t][0] = ax; acc[t][1] = ay; acc[t][2] = az; acc[t][3] = aw;
    }
    float* dst;
    float b0, b1, b2, b3;
    if (lane < 16) {
        dst = out + (size_t)n * (CO * TT) + lane * 32;   // d0 = 4*lane, offset d0*8
        b0 = sbias[4 * lane]; b1 = sbias[4 * lane + 1]; b2 = sbias[4 * lane + 2]; b3 = sbias[4 * lane + 3];
    } else {
        dst = g_y1 + (size_t)n * (CO * TT) + (lane - 16) * 32;
        b0 = b1 = b2 = b3 = 0.f;
    }
    float bj[4] = {b0, b1, b2, b3};
#pragma unroll
    for (int j = 0; j < 4; j++) {
        float4 lo = make_float4(acc[0][j] + bj[j], acc[1][j] + bj[j], acc[2][j] + bj[j], acc[3][j] + bj[j]);
        float4 hi = make_float4(acc[4][j] + bj[j], acc[5][j] + bj[j], acc[6][j] + bj[j], acc[7][j] + bj[j]);
        ((float4*)dst)[j * 2] = lo;
        ((float4*)dst)[j * 2 + 1] = hi;
    }
}

// ---------------- atomic-free gather: out[n] += sum_e w_e * y1[src_e] ----------------
__global__ void k_gather(float* __restrict__ out) {
    int n = blockIdx.x;
    int tid = threadIdx.x;   // 128 threads x float4 = 512 floats per node
    int beg = g_rowptr[n], end = g_rowptr[n + 1];
    float4 acc = make_float4(0.f, 0.f, 0.f, 0.f);
    for (int e = beg; e < end; e++) {
        int s = g_col[e];
        float wv = g_wgt[e];
        float4 v = __ldg((const float4*)(g_y1 + (size_t)s * (CO * TT)) + tid);
        acc.x = __fmaf_rn(wv, v.x, acc.x);
        acc.y = __fmaf_rn(wv, v.y, acc.y);
        acc.z = __fmaf_rn(wv, v.z, acc.z);
        acc.w = __fmaf_rn(wv, v.w, acc.w);
    }
    float4* o = (float4*)(out + (size_t)n * (CO * TT)) + tid;
    float4 cur = *o;
    cur.x += acc.x; cur.y += acc.y; cur.z += acc.z; cur.w += acc.w;
    *o = cur;
}

// ---------------- launch ----------------
extern "C" void kernel_launch(void* const* d_in, const int* in_sizes, int n_in,
                              void* d_out, int out_size) {
    const float* x     = (const float*)d_in[0];
    const int*   ei    = (const int*)d_in[1];
    const float* gamma = (const float*)d_in[2];
    const float* beta  = (const float*)d_in[3];
    const float* W0    = (const float*)d_in[4];
    const float* W1    = (const float*)d_in[5];
    const float* bias  = (const float*)d_in[6];
    float* out = (float*)d_out;

    k_zero  <<<(NN + 255) / 256, 256>>>();
    k_detect<<<1, 256>>>((const unsigned*)ei);
    k_stats <<<1024, 256>>>(x);                 // stride 262144 (multiple of 128)
    k_final <<<1, 128>>>();
    k_lut   <<<16 * 256, 128>>>(W0, W1);
    k_lif   <<<NN / 8, 256>>>(x, gamma, beta);
    k_deg   <<<(EE + 255) / 256, 256>>>(ei);
    k_scan  <<<1, 1024>>>();
    k_csr   <<<(EE + 255) / 256, 256>>>(ei);
    k_gemm  <<<NN / 8, 256>>>(out, bias);
    k_gather<<<NN, 128>>>(out);
}

// round 8
// speedup vs baseline: 1.0078x; 1.0058x over previous
#include <cuda_runtime.h>
#include <cstdint>

#define NN 20000     // nodes
#define CI 128       // in channels
#define TT 8         // time steps
#define CO 64        // out channels
#define EE 160000    // edges

// ---------------- scratch (static device globals; no allocation) ----------------
__device__ double   g_sum[CI];
__device__ double   g_sumsq[CI];
__device__ float    g_mean[CI];
__device__ float    g_rs[CI];                 // rsqrt(var + eps)
__device__ unsigned g_bits[NN * 32];          // spike bits: [n][t*4+k], bit l = spike(c=l+32k, t)
__device__ int      g_deg[NN];
__device__ float    g_dinv[NN];
__device__ int      g_rowptr[NN + 1];
__device__ int      g_cursor[NN];
__device__ int      g_col[EE];
__device__ float    g_wgt[EE];
__device__ float    g_y1[(size_t)NN * CO * TT];   // s @ W1^T  [n][d][t]
__device__ float    g_lut[16 * 256 * 128];        // lut[g][m][dcomb]; dcomb<64 -> W0, else W1
__device__ int      g_is64;

// ---------------- init ----------------
__global__ void k_zero() {
    int i = blockIdx.x * blockDim.x + threadIdx.x;
    if (i < CI) { g_sum[i] = 0.0; g_sumsq[i] = 0.0; }
    if (i < NN) g_deg[i] = 0;
}

// Detect int64 vs int32 edge_index: int64 little-endian => every odd 32-bit word
// of the first values is a zero high-half.
__global__ void k_detect(const unsigned* __restrict__ ei) {
    __shared__ int s_nz;
    if (threadIdx.x == 0) s_nz = 0;
    __syncthreads();
    for (int i = threadIdx.x; i < 256; i += blockDim.x)
        if (ei[2 * i + 1] != 0u) atomicOr(&s_nz, 1);
    __syncthreads();
    if (threadIdx.x == 0) g_is64 = (s_nz == 0) ? 1 : 0;
}

// ---------------- BN stats (fp64 accumulate; channel fixed per thread) ----------------
__global__ void k_stats(const float* __restrict__ x) {
    int tid = blockIdx.x * blockDim.x + threadIdx.x;
    int stride = gridDim.x * blockDim.x;   // launch so stride % 128 == 0
    double s = 0.0, q = 0.0;
    for (int r = tid; r < NN * CI; r += stride) {
        const float4* p = (const float4*)(x + (size_t)r * TT);
        float4 a = p[0], b = p[1];
        s += (double)a.x + (double)a.y + (double)a.z + (double)a.w
           + (double)b.x + (double)b.y + (double)b.z + (double)b.w;
        q += (double)a.x * a.x + (double)a.y * a.y + (double)a.z * a.z + (double)a.w * a.w
           + (double)b.x * b.x + (double)b.y * b.y + (double)b.z * b.z + (double)b.w * b.w;
    }
    int c = tid & 127;   // constant per thread because stride % 128 == 0
    atomicAdd(&g_sum[c], s);
    atomicAdd(&g_sumsq[c], q);
}

__global__ void k_final() {
    int c = threadIdx.x;
    if (c < CI) {
        double cnt = (double)NN * (double)TT;
        double m = g_sum[c] / cnt;
        double var = g_sumsq[c] / cnt - m * m;
        g_mean[c] = (float)m;
        g_rs[c] = (float)(1.0 / sqrt(var + 1e-5));
    }
}

// ---------------- LUT build: lut[g][m][d] = sum_{i: bit i of m} W[d][8g+i] ----------------
__global__ void k_lut(const float* __restrict__ W0, const float* __restrict__ W1) {
    int d = threadIdx.x;                  // 0..127 combined output
    int gm = blockIdx.x;                  // g*256 + m
    int g = gm >> 8;
    int m = gm & 255;
    const float* W = (d < CO) ? (W0 + (size_t)d * CI) : (W1 + (size_t)(d - CO) * CI);
    int cb = g * 8;
    float s = 0.f;
#pragma unroll
    for (int i = 0; i < 8; i++)
        if (m & (1 << i)) s += __ldg(&W[cb + i]);
    g_lut[(size_t)gm * 128 + d] = s;
}

// ---------------- normalize + LIF + bit-pack (warp per node) ----------------
__global__ void k_lif(const float* __restrict__ x,
                      const float* __restrict__ gamma,
                      const float* __restrict__ beta) {
    __shared__ float sm[CI], sr[CI], sg[CI], sb[CI];
    int tid = threadIdx.x;
    if (tid < CI) { sm[tid] = g_mean[tid]; sr[tid] = g_rs[tid]; sg[tid] = gamma[tid]; sb[tid] = beta[tid]; }
    __syncthreads();
    int lane = tid & 31;
    int n = blockIdx.x * 8 + (tid >> 5);
    unsigned sp8[4];
#pragma unroll
    for (int k = 0; k < 4; k++) {
        int c = lane + 32 * k;
        const float4* p = (const float4*)(x + (size_t)n * (CI * TT) + (size_t)c * TT);
        float4 a = p[0], b = p[1];
        float m = sm[c], rs = sr[c], ga = sg[c], be = sb[c];
        float h[8];
        // exact reference op order: (gamma*(x-mean))*rsqrt + beta   (no fma contraction)
        h[0] = __fadd_rn(__fmul_rn(__fmul_rn(ga, __fsub_rn(a.x, m)), rs), be);
        h[1] = __fadd_rn(__fmul_rn(__fmul_rn(ga, __fsub_rn(a.y, m)), rs), be);
        h[2] = __fadd_rn(__fmul_rn(__fmul_rn(ga, __fsub_rn(a.z, m)), rs), be);
        h[3] = __fadd_rn(__fmul_rn(__fmul_rn(ga, __fsub_rn(a.w, m)), rs), be);
        h[4] = __fadd_rn(__fmul_rn(__fmul_rn(ga, __fsub_rn(b.x, m)), rs), be);
        h[5] = __fadd_rn(__fmul_rn(__fmul_rn(ga, __fsub_rn(b.y, m)), rs), be);
        h[6] = __fadd_rn(__fmul_rn(__fmul_rn(ga, __fsub_rn(b.z, m)), rs), be);
        h[7] = __fadd_rn(__fmul_rn(__fmul_rn(ga, __fsub_rn(b.w, m)), rs), be);
        float mem = 0.f, spf = 0.f;
        unsigned msk = 0u;
#pragma unroll
        for (int t = 0; t < 8; t++) {
            mem = __fadd_rn(__fmul_rn(__fmul_rn(mem, 0.2f), __fsub_rn(1.f, spf)), h[t]);
            bool s = (mem > 0.5f);
            spf = s ? 1.f : 0.f;
            msk |= (s ? 1u : 0u) << t;
        }
        sp8[k] = msk;
    }
    unsigned myw = 0u;
#pragma unroll
    for (int idx = 0; idx < 32; idx++) {
        unsigned pred = (sp8[idx & 3] >> (idx >> 2)) & 1u;
        unsigned bal = __ballot_sync(0xffffffffu, pred);
        if (lane == idx) myw = bal;
    }
    g_bits[n * 32 + lane] = myw;
}

// ---------------- degree, scan, CSR build ----------------
__global__ void k_deg(const int* __restrict__ ei) {
    int e = blockIdx.x * blockDim.x + threadIdx.x;
    if (e >= EE) return;
    int is64 = g_is64;
    int d = is64 ? ei[2 * (EE + e)] : ei[EE + e];
    atomicAdd(&g_deg[d], 1);
}

__global__ void k_scan() {
    __shared__ int wsum[32];
    __shared__ int s_off;
    int tid = threadIdx.x, lane = tid & 31, w = tid >> 5;
    if (tid == 0) s_off = 0;
    __syncthreads();
    for (int base = 0; base < NN; base += 1024) {
        int i = base + tid;
        int v = (i < NN) ? g_deg[i] : 0;
        int inc = v;
#pragma unroll
        for (int d = 1; d < 32; d <<= 1) {
            int t = __shfl_up_sync(0xffffffffu, inc, d);
            if (lane >= d) inc += t;
        }
        if (lane == 31) wsum[w] = inc;
        __syncthreads();
        if (w == 0) {
            int xv = wsum[lane];
#pragma unroll
            for (int d = 1; d < 32; d <<= 1) {
                int t = __shfl_up_sync(0xffffffffu, xv, d);
                if (lane >= d) xv += t;
            }
            wsum[lane] = xv;
        }
        __syncthreads();
        int off = s_off + (w ? wsum[w - 1] : 0);
        int excl = off + inc - v;
        if (i < NN) {
            g_rowptr[i] = excl;
            g_cursor[i] = excl;
            g_dinv[i] = (v > 0) ? rsqrtf((float)v) : 0.f;
        }
        __syncthreads();
        if (tid == 0) s_off += wsum[31];
        __syncthreads();
    }
    if (threadIdx.x == 0) g_rowptr[NN] = s_off;
}

__global__ void k_csr(const int* __restrict__ ei) {
    int e = blockIdx.x * blockDim.x + threadIdx.x;
    if (e >= EE) return;
    int is64 = g_is64;
    int s = is64 ? ei[2 * e] : ei[e];
    int d = is64 ? ei[2 * (EE + e)] : ei[EE + e];
    int pos = atomicAdd(&g_cursor[d], 1);
    g_col[pos] = s;
    g_wgt[pos] = __fmul_rn(g_dinv[s], g_dinv[d]);
}

// ---------------- GEMM via 8-bit LUT (warp per node) ----------------
// out[n][d][t]      = sum_c s(n,c,t) W0[d][c] + b[d]      (d < 64 half)
// g_y1[n][d][t]     = sum_c s(n,c,t) W1[d][c]             (d >= 64 half)
__global__ void k_gemm(float* __restrict__ out, const float* __restrict__ bias) {
    __shared__ float sbias[CO];
    int tid = threadIdx.x;
    if (tid < CO) sbias[tid] = bias[tid];
    __syncthreads();
    int lane = tid & 31;
    int n = blockIdx.x * 8 + (tid >> 5);
    unsigned myw = g_bits[n * 32 + lane];
    float acc[8][4];
#pragma unroll
    for (int t = 0; t < 8; t++) {
        float ax = 0.f, ay = 0.f, az = 0.f, aw = 0.f;
#pragma unroll
        for (int k = 0; k < 4; k++) {
            unsigned wv = __shfl_sync(0xffffffffu, myw, t * 4 + k);
#pragma unroll
            for (int j = 0; j < 4; j++) {
                unsigned m = (wv >> (8 * j)) & 255u;
                int g = k * 4 + j;
                const float4 v = *(const float4*)(g_lut + ((((unsigned)g << 8) | m) << 7) + (lane << 2));
                ax += v.x; ay += v.y; az += v.z; aw += v.w;
            }
        }
        acc[t][0] = ax; acc[t][1] = ay; acc[t][2] = az; acc[t][3] = aw;
    }
    float* dst;
    float b0, b1, b2, b3;
    if (lane < 16) {
        dst = out + (size_t)n * (CO * TT) + lane * 32;   // d0 = 4*lane, offset d0*8
        b0 = sbias[4 * lane]; b1 = sbias[4 * lane + 1]; b2 = sbias[4 * lane + 2]; b3 = sbias[4 * lane + 3];
    } else {
        dst = g_y1 + (size_t)n * (CO * TT) + (lane - 16) * 32;
        b0 = b1 = b2 = b3 = 0.f;
    }
    float bj[4] = {b0, b1, b2, b3};
#pragma unroll
    for (int j = 0; j < 4; j++) {
        float4 lo = make_float4(acc[0][j] + bj[j], acc[1][j] + bj[j], acc[2][j] + bj[j], acc[3][j] + bj[j]);
        float4 hi = make_float4(acc[4][j] + bj[j], acc[5][j] + bj[j], acc[6][j] + bj[j], acc[7][j] + bj[j]);
        ((float4*)dst)[j * 2] = lo;
        ((float4*)dst)[j * 2 + 1] = hi;
    }
}

// ---------------- atomic-free gather: out[n] += sum_e w_e * y1[src_e] ----------------
__global__ void k_gather(float* __restrict__ out) {
    int n = blockIdx.x;
    int tid = threadIdx.x;   // 128 threads x float4 = 512 floats per node
    int beg = g_rowptr[n], end = g_rowptr[n + 1];
    float4 acc = make_float4(0.f, 0.f, 0.f, 0.f);
    for (int e = beg; e < end; e++) {
        int s = g_col[e];
        float wv = g_wgt[e];
        float4 v = __ldg((const float4*)(g_y1 + (size_t)s * (CO * TT)) + tid);
        acc.x = __fmaf_rn(wv, v.x, acc.x);
        acc.y = __fmaf_rn(wv, v.y, acc.y);
        acc.z = __fmaf_rn(wv, v.z, acc.z);
        acc.w = __fmaf_rn(wv, v.w, acc.w);
    }
    float4* o = (float4*)(out + (size_t)n * (CO * TT)) + tid;
    float4 cur = *o;
    cur.x += acc.x; cur.y += acc.y; cur.z += acc.z; cur.w += acc.w;
    *o = cur;
}

// ---------------- launch ----------------
extern "C" void kernel_launch(void* const* d_in, const int* in_sizes, int n_in,
                              void* d_out, int out_size) {
    const float* x     = (const float*)d_in[0];
    const int*   ei    = (const int*)d_in[1];
    const float* gamma = (const float*)d_in[2];
    const float* beta  = (const float*)d_in[3];
    const float* W0    = (const float*)d_in[4];
    const float* W1    = (const float*)d_in[5];
    const float* bias  = (const float*)d_in[6];
    float* out = (float*)d_out;

    k_zero  <<<(NN + 255) / 256, 256>>>();
    k_detect<<<1, 256>>>((const unsigned*)ei);
    k_stats <<<1024, 256>>>(x);                 // stride 262144 (multiple of 128)
    k_final <<<1, 128>>>();
    k_lut   <<<16 * 256, 128>>>(W0, W1);
    k_lif   <<<NN / 8, 256>>>(x, gamma, beta);
    k_deg   <<<(EE + 255) / 256, 256>>>(ei);
    k_scan  <<<1, 1024>>>();
    k_csr   <<<(EE + 255) / 256, 256>>>(ei);
    k_gemm  <<<NN / 8, 256>>>(out, bias);
    k_gather<<<NN, 128>>>(out);
}